// round 6
// baseline (speedup 1.0000x reference)
#include <cuda_runtime.h>
#include <float.h>

// ROI adaptive max pool 7x7 — separable, float4, work-compacted phase 1.
// images: [8,256,56,56] f32; rois: [256,4] f32; roi_idx: [256] i32
// out: [256,256,7,7] f32
//
// Block = (roi, 16-channel group), 256 threads (flat).
// Phase 1 work items = (bin, channel, active-quad), enumerated in a shared
// LUT (built without divisions), grid-strided by all threads: ~90% lane
// efficiency vs ~37% for the fixed quad-slot mapping. Consecutive lanes =
// consecutive quads of one channel -> coalesced float4 segments; a warp
// stays mostly within one bin -> near-uniform (s,e).
// Phase 2: col-bin maxes from shared rowp, coalesced stores.

#define Hc 56
#define Wc 56
#define Cc 256
#define Rc 256
#define OUTN 7
#define CPB 16
#define W4 (Wc / 4)        // 14
#define CHW4 (Hc * W4)     // 784 float4s per channel

__global__ __launch_bounds__(256, 7) void roipool_kernel(
    const float* __restrict__ images,
    const float* __restrict__ rois,
    const int* __restrict__ roi_idx,
    float* __restrict__ out)
{
    __shared__ float rowp[CPB][OUTN][60];
    __shared__ int sb[28];                      // ys[7] ye[7] xs[7] xe[7]
    __shared__ unsigned short items[CPB * 14 * OUTN];  // max 1568 entries

    const int r   = blockIdx.y;
    const int cg  = blockIdx.x;
    const int tid = threadIdx.x;

    const float4 rv = ((const float4*)rois)[r];
    const int x1 = (int)floorf(rv.x * (float)Wc);
    const int y1 = (int)floorf(rv.y * (float)Hc);
    const int x2 = (int)ceilf (rv.z * (float)Wc);
    const int y2 = (int)ceilf (rv.w * (float)Hc);

    const int qlo = x1 >> 2;
    const int qhi = (x2 + 3) >> 2;
    const int nq  = qhi - qlo;                  // 0..14 active quads
    const int nItems = OUTN * CPB * nq;

    // Bin-bounds table (28 threads, one entry each)
    if (tid < 28) {
        const int g = tid / OUTN;               // 0:ys 1:ye 2:xs 3:xe
        const int i = tid - g * OUTN;
        const int Hr = y2 - y1, Wr = x2 - x1;
        int v;
        if (g == 0)      v = y1 + (i * Hr) / OUTN;
        else if (g == 1) v = y1 + ((i + 1) * Hr + OUTN - 1) / OUTN;
        else if (g == 2) v = x1 + (i * Wr) / OUTN;
        else             v = x1 + ((i + 1) * Wr + OUTN - 1) / OUTN;
        sb[tid] = v;
    }

    // Item LUT: bin-major, channel, quad-innermost. No divisions.
    if (tid < OUTN * CPB) {
        const int bin = tid >> 4;               // tid / 16
        const int ch  = tid & 15;
        unsigned short* it = items + (bin * CPB + ch) * nq;
        const unsigned short base = (unsigned short)((ch << 8) | bin);
        for (int q = 0; q < nq; q++)
            it[q] = (unsigned short)(base | (q << 4));
    }
    __syncthreads();

    const int n = roi_idx[r];
    const float4* __restrict__ imgbase =
        (const float4*)images + (size_t)(n * Cc + cg * CPB) * CHW4;

    // ---- Phase 1: compacted row-bin maxes ----
    for (int w = tid; w < nItems; w += 256) {
        const int pk  = items[w];
        const int ch  = pk >> 8;
        const int q   = (pk >> 4) & 15;
        const int bin = pk & 7;
        const int s = sb[bin], e = sb[7 + bin];
        const float4* p = imgbase + ch * CHW4 + (qlo + q) + s * W4;
        float4 m = make_float4(-FLT_MAX, -FLT_MAX, -FLT_MAX, -FLT_MAX);
        #pragma unroll 4
        for (int y = s; y < e; y++) {
            const float4 v = *p; p += W4;
            m.x = fmaxf(m.x, v.x);
            m.y = fmaxf(m.y, v.y);
            m.z = fmaxf(m.z, v.z);
            m.w = fmaxf(m.w, v.w);
        }
        *(float4*)&rowp[ch][bin][(qlo + q) * 4] = m;
    }
    __syncthreads();

    // ---- Phase 2: col-bin maxes from shared ----
    float* __restrict__ outg = out + ((size_t)r * Cc + cg * CPB) * (OUTN * OUTN);
    #pragma unroll
    for (int o = tid; o < CPB * OUTN * OUTN; o += 256) {
        const int cc = o / (OUTN * OUTN);
        const int ij = o - cc * (OUTN * OUTN);
        const int i = ij / OUTN;
        const int j = ij - i * OUTN;
        const int s = sb[14 + j], e = sb[21 + j];
        float m = -FLT_MAX;
        for (int x = s; x < e; x++)
            m = fmaxf(m, rowp[cc][i][x]);
        outg[o] = m;   // contiguous per stride-pass -> coalesced
    }
}

extern "C" void kernel_launch(void* const* d_in, const int* in_sizes, int n_in,
                              void* d_out, int out_size) {
    const float* images  = (const float*)d_in[0];
    const float* rois    = (const float*)d_in[1];
    const int*   roi_idx = (const int*)d_in[2];
    float* out = (float*)d_out;

    dim3 grid(Cc / CPB, Rc);   // (16, 256) = 4096 blocks
    roipool_kernel<<<grid, 256>>>(images, rois, roi_idx, out);
}